// round 11
// baseline (speedup 1.0000x reference)
#include <cuda_runtime.h>
#include <math.h>

#define HID 256
#define QN 64
#define LQ 20
#define DN 24
#define LD 50
#define QROWS (QN*LQ)   // 1280
#define DROWS (DN*LD)   // 1200

typedef unsigned long long u64;

__device__ __forceinline__ u64 ffma2(u64 a, u64 b, u64 c) {
    u64 d; asm("fma.rn.f32x2 %0, %1, %2, %3;" : "=l"(d) : "l"(a), "l"(b), "l"(c)); return d;
}
__device__ __forceinline__ float hsum2(u64 s) {
    float lo, hi; asm("mov.b64 {%0, %1}, %2;" : "=f"(lo), "=f"(hi) : "l"(s)); return lo + hi;
}
__device__ __forceinline__ void unpack2(u64 s, float& lo, float& hi) {
    asm("mov.b64 {%0, %1}, %2;" : "=f"(lo), "=f"(hi) : "l"(s));
}
__device__ __forceinline__ u64 dupf(float v) {
    u64 d; asm("mov.b64 %0, {%1, %1};" : "=l"(d) : "f"(v)); return d;
}
__device__ __forceinline__ float dot4(float4 a, float4 b, float s) {
    s = fmaf(a.x, b.x, s); s = fmaf(a.y, b.y, s);
    s = fmaf(a.z, b.z, s); s = fmaf(a.w, b.w, s);
    return s;
}
__device__ __forceinline__ float sigf(float x) {
    return __fdividef(1.f, 1.f + __expf(-x));
}
__device__ __forceinline__ float tanhfast(float x) {
    return 1.f - __fdividef(2.f, __expf(2.f*x) + 1.f);
}
__device__ __forceinline__ unsigned ldflag(const unsigned* p) {
    unsigned v; asm volatile("ld.relaxed.gpu.global.u32 %0, [%1];" : "=r"(v) : "l"(p));
    return v;
}
__device__ __forceinline__ void stflag(unsigned* p, unsigned v) {
    asm volatile("st.relaxed.gpu.global.u32 [%0], %1;" :: "l"(p), "r"(v));
}
#define FENCE_GPU() asm volatile("fence.acq_rel.gpu;" ::: "memory")

// ---------------- scratch ----------------------------------------------------
__device__ __align__(16) float g_giq[QROWS*768];
__device__ __align__(16) float g_gic[DROWS*768];
__device__ __align__(16) float g_gia[DROWS*768];
__device__ __align__(16) float g_hd[2][48][256];    // doc h payload (parity)
__device__ __align__(16) float g_hx[2][64][256];    // query h payload (parity)
__device__ __align__(16) unsigned g_fd[6][16];      // doc flags: [group][cta]
__device__ __align__(16) unsigned g_fq[8][8];       // query flags
__device__ __align__(16) float g_hcf[DN*HID];
__device__ __align__(16) float g_haf[DN*HID];
__device__ __align__(16) float g_hqf[QN*HID];
__device__ __align__(16) float g_cfin[DN*HID];
__device__ __align__(16) float g_qpn[QN*HID];
__device__ __align__(16) unsigned g_bar[512];

// ---------------- K1: gi = emb[tok] @ W^T + b, gather fused, f32x2 -----------
#define GBM 128
#define GBN 192
#define GBK 32
#define ASD 132
#define BSD 196

__global__ void __launch_bounds__(256) gi_gemm_k(
    const int* __restrict__ qt, const int* __restrict__ pt, const int* __restrict__ nt,
    const float* __restrict__ temb, const float* __restrict__ demb,
    const float* __restrict__ tW, const float* __restrict__ tb,
    const float* __restrict__ cW, const float* __restrict__ cb,
    const float* __restrict__ aW, const float* __restrict__ ab) {
    __shared__ float As[GBK*ASD];
    __shared__ float Bs[GBK*BSD];
    __shared__ int toks[GBM];

    int bid = blockIdx.x;
    int tid = threadIdx.x;
    // reset flags + tail barriers each replay (scan_k runs after this in-stream)
    if (bid == 0) {
        if (tid < 128) ((float4*)g_bar)[tid] = make_float4(0.f,0.f,0.f,0.f);
        if (tid < 96)  ((unsigned*)g_fd)[tid] = 0u;
        if (tid < 64)  ((unsigned*)g_fq)[tid] = 0u;
    }

    int seg = bid / 40;          // 0=query, 1=doc-c, 2=doc-a
    int rem = bid - seg*40;
    int mtl = rem >> 2, ntl = rem & 3;
    int m0 = mtl*GBM, n0 = ntl*GBN;

    const float* W; const float* bias; float* C; const float* emb; int M;
    if (seg == 0)      { W=tW; bias=tb; C=g_giq; emb=temb; M=QROWS; }
    else if (seg == 1) { W=cW; bias=cb; C=g_gic; emb=demb; M=DROWS; }
    else               { W=aW; bias=ab; C=g_gia; emb=demb; M=DROWS; }

    if (tid < GBM) {
        int m = m0 + tid;
        int tk = 0;
        if (m < M) {
            if (seg == 0) tk = qt[m];
            else tk = (m < 600) ? pt[m] : nt[m-600];
        }
        toks[tid] = tk;
    }
    __syncthreads();

    int tx = tid & 15, ty = tid >> 4;
    u64 acc2[4][12];
    #pragma unroll
    for (int p = 0; p < 4; p++)
        #pragma unroll
        for (int j = 0; j < 12; j++) acc2[p][j] = 0ull;

    for (int k0 = 0; k0 < HID; k0 += GBK) {
        #pragma unroll
        for (int q = 0; q < 4; q++) {
            int idx = q*256 + tid;
            int kq = idx >> 7, m = idx & 127;
            float4 v = make_float4(0.f,0.f,0.f,0.f);
            if (m0 + m < M) v = *(const float4*)(emb + (size_t)toks[m]*HID + k0 + kq*4);
            As[(kq*4+0)*ASD + m] = v.x; As[(kq*4+1)*ASD + m] = v.y;
            As[(kq*4+2)*ASD + m] = v.z; As[(kq*4+3)*ASD + m] = v.w;
        }
        #pragma unroll
        for (int q = 0; q < 6; q++) {
            int idx = q*256 + tid;
            int kq = idx / 192, n = idx - kq*192;
            float4 v = *(const float4*)(W + (size_t)(n0+n)*HID + k0 + kq*4);
            Bs[(kq*4+0)*BSD + n] = v.x; Bs[(kq*4+1)*BSD + n] = v.y;
            Bs[(kq*4+2)*BSD + n] = v.z; Bs[(kq*4+3)*BSD + n] = v.w;
        }
        __syncthreads();
        #pragma unroll 8
        for (int k = 0; k < GBK; k++) {
            ulonglong2 A01 = *(const ulonglong2*)(As + k*ASD + ty*8);
            ulonglong2 A23 = *(const ulonglong2*)(As + k*ASD + ty*8 + 4);
            u64 a2[4] = {A01.x, A01.y, A23.x, A23.y};
            float4 b0 = *(const float4*)(Bs + k*BSD + tx*4);
            float4 b1 = *(const float4*)(Bs + k*BSD + 64 + tx*4);
            float4 b2 = *(const float4*)(Bs + k*BSD + 128 + tx*4);
            u64 bb[12];
            bb[0]=dupf(b0.x); bb[1]=dupf(b0.y); bb[2]=dupf(b0.z); bb[3]=dupf(b0.w);
            bb[4]=dupf(b1.x); bb[5]=dupf(b1.y); bb[6]=dupf(b1.z); bb[7]=dupf(b1.w);
            bb[8]=dupf(b2.x); bb[9]=dupf(b2.y); bb[10]=dupf(b2.z); bb[11]=dupf(b2.w);
            #pragma unroll
            for (int p = 0; p < 4; p++)
                #pragma unroll
                for (int j = 0; j < 12; j++)
                    acc2[p][j] = ffma2(a2[p], bb[j], acc2[p][j]);
        }
        __syncthreads();
    }

    float4 bv[3];
    #pragma unroll
    for (int g = 0; g < 3; g++)
        bv[g] = *(const float4*)(bias + n0 + g*64 + tx*4);
    #pragma unroll
    for (int p = 0; p < 4; p++) {
        float vlo[12], vhi[12];
        #pragma unroll
        for (int j = 0; j < 12; j++) unpack2(acc2[p][j], vlo[j], vhi[j]);
        #pragma unroll
        for (int e = 0; e < 2; e++) {
            int m = m0 + ty*8 + p*2 + e;
            if (m >= M) continue;
            const float* vv = e ? vhi : vlo;
            #pragma unroll
            for (int g = 0; g < 3; g++) {
                float4 o;
                o.x = vv[g*4+0] + (&bv[g].x)[0];
                o.y = vv[g*4+1] + (&bv[g].x)[1];
                o.z = vv[g*4+2] + (&bv[g].x)[2];
                o.w = vv[g*4+3] + (&bv[g].x)[3];
                *(float4*)(C + (size_t)m*768 + n0 + g*64 + tx*4) = o;
            }
        }
    }
}

// ---------------- K2: GRU scans (flag+payload exchange) + fused tail ---------
__device__ __forceinline__ void bar_arrive_wait(unsigned* p, unsigned need) {
    asm volatile("red.release.gpu.global.add.u32 [%0], %1;" :: "l"(p), "r"(1u) : "memory");
    unsigned v;
    do {
        asm volatile("ld.acquire.gpu.global.u32 %0, [%1];" : "=r"(v) : "l"(p) : "memory");
    } while (v < need);
}

__global__ void __launch_bounds__(512) scan_k(
    const float* __restrict__ tWhh, const float* __restrict__ tbhh,
    const float* __restrict__ cWhh, const float* __restrict__ cbhh,
    const float* __restrict__ aWhh, const float* __restrict__ abhh,
    const float* __restrict__ ptab, const float* __restrict__ posW,
    const float* __restrict__ posb,
    const float* __restrict__ qWih, const float* __restrict__ qbih,
    const float* __restrict__ qbhh, float* __restrict__ out) {
    __shared__ __align__(16) float pool[6240];   // hs(4096)+parts(1632); tail reuses
    float* hs = pool;
    float* parts = pool + 4096;

    int bid = blockIdx.x, tid = threadIdx.x;
    bool isQ = (bid >= 96);
    int lane = tid & 31;
    int r = lane & 7, ks = lane >> 3;
    int row = (tid >> 5)*8 + r;
    bool act = tid < 384;

    int bg, c0, T, PB;
    unsigned* flags; unsigned* myflag; int need;
    if (!isQ) {
        bg = bid >> 4; c0 = (bid & 15) << 4; T = LD; PB = 5;
        flags = g_fd[bg]; myflag = &g_fd[bg][bid & 15]; need = 16;
    } else {
        int qg = bid - 96; bg = qg >> 3; c0 = (qg & 7) << 5; T = LQ; PB = 17;
        flags = g_fq[bg]; myflag = &g_fq[bg][qg & 7]; need = 8;
    }

    // ---- W slice into registers (rotated chunks, conflict-free h LDS) -------
    u64 wreg[32];
    int hrow0 = 0;
    if (act) {
        const float* Wp; int grow;
        if (!isQ) {
            int chain = row / 48, rr = row - (row/48)*48;
            grow = (rr >> 4)*256 + c0 + (rr & 15);
            Wp = chain ? aWhh : cWhh;
            hrow0 = chain * 4;
        } else {
            grow = (row >> 5)*256 + c0 + (row & 31);
            Wp = tWhh;
        }
        const float* base = Wp + (size_t)grow*HID + ks*64;
        #pragma unroll
        for (int i = 0; i < 8; i++) {
            int ch = (i + ks) & 7;
            ulonglong2 p0 = *(const ulonglong2*)(base + ch*8);
            ulonglong2 p1 = *(const ulonglong2*)(base + ch*8 + 4);
            wreg[i*4+0]=p0.x; wreg[i*4+1]=p0.y; wreg[i*4+2]=p1.x; wreg[i*4+3]=p1.y;
        }
    }

    // ---- phase-2 (producer) setup -------------------------------------------
    bool oact; int prI=0, pzI=0, pnI=0, hpI=0, hoff=0, cc=0, prow=0;
    float br=0.f, bz=0.f, bn=0.f;
    const float* giBase = nullptr;
    int docChain = 0;
    if (!isQ) {
        oact = (tid < 128);
        if (oact) {
            int chain = tid >> 6, b = (tid >> 4) & 3, cl = tid & 15;
            docChain = chain;
            cc = c0 + cl;
            prI = (chain*48 + cl)*PB + b; pzI = prI + 16*PB; pnI = prI + 32*PB;
            hpI = (chain*4 + b)*256 + cc;
            const float* bh = chain ? abhh : cbhh;
            br = bh[cc]; bz = bh[256+cc]; bn = bh[512+cc];
            giBase = (chain ? g_gia : g_gic) + (size_t)(bg*4 + b)*LD*768;
            hoff = (bg*4 + b)*256 + cc;
            prow = chain*24 + bg*4 + b;
        }
    } else {
        oact = true;
        int b = tid >> 5, cl = tid & 31;
        cc = c0 + cl;
        prI = cl*PB + b; pzI = (32+cl)*PB + b; pnI = (64+cl)*PB + b;
        hpI = b*256 + cc;
        br = tbhh[cc]; bz = tbhh[256+cc]; bn = tbhh[512+cc];
        giBase = g_giq + (size_t)(bg*16 + b)*LQ*768;
        hoff = (bg*16 + b)*256 + cc;
        prow = bg*16 + b;
    }

    // staging map
    int slrow, sc4, sgrow;
    if (!isQ) {
        slrow = tid >> 6; sc4 = (tid & 63) << 2;
        int chain = slrow >> 2, bb = slrow & 3;
        sgrow = chain*24 + bg*4 + bb;
    } else {
        slrow = 0; sc4 = 0; sgrow = bg*16;   // computed inline below
    }

    // ---- zero hs (h0 = 0) -----------------------------------------------------
    #pragma unroll
    for (int i = 0; i < 2; i++)
        ((float4*)hs)[tid + i*512] = make_float4(0.f,0.f,0.f,0.f);
    __syncthreads();

    for (int t = 0; t < T; t++) {
        int cur = t & 1;
        // gi prefetch (independent of h)
        float xr=0.f, xz=0.f, xn=0.f;
        if (oact) {
            const float* gp = giBase + (size_t)t*768;
            xr = gp[cc]; xz = gp[256+cc]; xn = gp[512+cc];
        }
        if (t > 0) {
            // flag poll: few lanes, one 32-bit word each
            if (tid < need) {
                unsigned v;
                do { v = ldflag(flags + tid); } while (v < (unsigned)t);
                FENCE_GPU();
            }
            __syncthreads();
            // stage h(t) with coalesced ld.cg
            if (!isQ) {
                float4 v = __ldcg((const float4*)&g_hd[cur][sgrow][sc4]);
                *(float4*)(hs + slrow*256 + sc4) = v;
            } else {
                #pragma unroll
                for (int i = 0; i < 2; i++) {
                    int idx = tid + i*512;
                    int lr = idx >> 6, c4 = (idx & 63) << 2;
                    float4 v = __ldcg((const float4*)&g_hx[cur][bg*16 + lr][c4]);
                    *(float4*)(hs + lr*256 + c4) = v;
                }
            }
            __syncthreads();
        }
        // ---- phase 1 ----
        if (act) {
            if (!isQ) {
                u64 acc[4];
                #pragma unroll
                for (int b = 0; b < 4; b++) acc[b] = 0ull;
                #pragma unroll
                for (int i = 0; i < 8; i++) {
                    int off = ((i + ks) & 7) * 8 + ks*64;
                    #pragma unroll
                    for (int b = 0; b < 4; b++) {
                        const float* hp = hs + (hrow0 + b)*256 + off;
                        ulonglong2 h0 = *(const ulonglong2*)hp;
                        ulonglong2 h1 = *(const ulonglong2*)(hp + 4);
                        acc[b] = ffma2(h0.x, wreg[i*4+0], acc[b]);
                        acc[b] = ffma2(h0.y, wreg[i*4+1], acc[b]);
                        acc[b] = ffma2(h1.x, wreg[i*4+2], acc[b]);
                        acc[b] = ffma2(h1.y, wreg[i*4+3], acc[b]);
                    }
                }
                #pragma unroll
                for (int b = 0; b < 4; b++) {
                    float s = hsum2(acc[b]);
                    s += __shfl_xor_sync(0xffffffffu, s, 8);
                    s += __shfl_xor_sync(0xffffffffu, s, 16);
                    if (ks == 0) parts[row*5 + b] = s;
                }
            } else {
                #pragma unroll
                for (int half = 0; half < 2; half++) {
                    u64 acc[8];
                    #pragma unroll
                    for (int b = 0; b < 8; b++) acc[b] = 0ull;
                    #pragma unroll
                    for (int i = 0; i < 8; i++) {
                        int off = ((i + ks) & 7) * 8 + ks*64;
                        #pragma unroll
                        for (int b = 0; b < 8; b++) {
                            const float* hp = hs + (half*8 + b)*256 + off;
                            ulonglong2 h0 = *(const ulonglong2*)hp;
                            ulonglong2 h1 = *(const ulonglong2*)(hp + 4);
                            acc[b] = ffma2(h0.x, wreg[i*4+0], acc[b]);
                            acc[b] = ffma2(h0.y, wreg[i*4+1], acc[b]);
                            acc[b] = ffma2(h1.x, wreg[i*4+2], acc[b]);
                            acc[b] = ffma2(h1.y, wreg[i*4+3], acc[b]);
                        }
                    }
                    #pragma unroll
                    for (int b = 0; b < 8; b++) {
                        float s = hsum2(acc[b]);
                        s += __shfl_xor_sync(0xffffffffu, s, 8);
                        s += __shfl_xor_sync(0xffffffffu, s, 16);
                        if (ks == 0) parts[row*17 + half*8 + b] = s;
                    }
                }
            }
        }
        __syncthreads();
        // ---- phase 2: gate; publish ----
        if (oact) {
            float ghr = br + parts[prI];
            float ghz = bz + parts[pzI];
            float ghn = bn + parts[pnI];
            float rr2 = sigf(xr + ghr);
            float zz = sigf(xz + ghz);
            float nn = tanhfast(xn + rr2*ghn);
            float hv = (1.f - zz)*nn + zz*hs[hpI];
            if (t + 1 < T) {
                if (!isQ) __stcg(&g_hd[(t+1)&1][prow][cc], hv);
                else      __stcg(&g_hx[(t+1)&1][prow][cc], hv);
            } else {
                if (!isQ) (docChain ? g_haf : g_hcf)[hoff] = hv;
                else      g_hqf[hoff] = hv;
            }
        }
        __syncthreads();
        if (t + 1 < T && tid == 0) {
            FENCE_GPU();
            stflag(myflag, (unsigned)(t + 1));
        }
    }

    // ================= fused tail =================
    __syncthreads();
    if (tid == 0) bar_arrive_wait(g_bar + 500, 128);
    __syncthreads();

    if (bid < 8) {
        float* in_s = pool;
        int c0p = bid * 32;
        for (int i = tid; i < 24*260; i += 512) {
            int d = i / 260, k = i - d*260;
            in_s[i] = (k < 256) ? g_hcf[d*256 + k] : ptab[(d % 12)*4 + (k - 256)];
        }
        __syncthreads();
        if (tid < 256) {
            int kg = tid & 7, cx = tid >> 3;
            int c = c0p + cx;
            int k0 = kg*33, k1 = (kg == 7) ? 260 : k0 + 33;
            float accp[24];
            #pragma unroll
            for (int d = 0; d < 24; d++) accp[d] = 0.f;
            const float* wr = posW + (size_t)c*260;
            for (int k = k0; k < k1; k++) {
                float wv = wr[k];
                #pragma unroll
                for (int d = 0; d < 24; d++) accp[d] = fmaf(wv, in_s[d*260 + k], accp[d]);
            }
            #pragma unroll
            for (int d = 0; d < 24; d++) {
                float s = accp[d];
                s += __shfl_xor_sync(0xffffffffu, s, 1);
                s += __shfl_xor_sync(0xffffffffu, s, 2);
                s += __shfl_xor_sync(0xffffffffu, s, 4);
                if (kg == 0) g_cfin[d*256 + c] = s + posb[c];
            }
        }
    } else if (bid < 72) {
        int q = bid - 8;
        float* enc = pool;
        float* wgt = pool + 256;
        if (tid < 256) enc[tid] = g_hqf[q*256 + tid];
        __syncthreads();
        if (tid < 192) {
            int d = tid >> 3, sg = tid & 7;
            const float4* ar = (const float4*)(g_haf + d*256 + sg*32);
            const float4* er = (const float4*)(enc + sg*32);
            float s = 0.f;
            #pragma unroll
            for (int i = 0; i < 8; i++) s = dot4(er[i], ar[i], s);
            s += __shfl_xor_sync(0xffffffffu, s, 1);
            s += __shfl_xor_sync(0xffffffffu, s, 2);
            s += __shfl_xor_sync(0xffffffffu, s, 4);
            if (sg == 0) wgt[d] = s;
        }
        __syncthreads();
        if (tid < 2) {
            int off = tid*12;
            float mx = -1e30f;
            for (int d = 0; d < 12; d++) mx = fmaxf(mx, wgt[off+d]);
            float sum = 0.f;
            for (int d = 0; d < 12; d++) { float e = __expf(wgt[off+d]-mx); wgt[off+d]=e; sum += e; }
            float inv = __fdividef(1.f, sum);
            for (int d = 0; d < 12; d++) wgt[off+d] *= inv;
        }
    }
    __syncthreads();
    if (tid == 0) bar_arrive_wait(g_bar + 501, 128);
    __syncthreads();

    if (bid >= 8 && bid < 72 && tid < 256) {
        int q = bid - 8;
        float* enc = pool;
        float* wgt = pool + 256;
        float v = enc[tid];
        #pragma unroll
        for (int d = 0; d < 24; d++) v = fmaf(wgt[d], g_cfin[d*256 + tid], v);
        g_qpn[q*256 + tid] = v;
    }
    __syncthreads();
    if (tid == 0) bar_arrive_wait(g_bar + 502, 128);
    __syncthreads();

    if (bid < 32) {
        float* res = pool;
        int c0g = bid * 8;
        if (tid < 256) {
            int w = tid >> 5, ln = tid & 31;
            int q = (w & 1)*32 + ln;
            int rg = w >> 1;
            u64 acc[6];
            #pragma unroll
            for (int j = 0; j < 6; j++) acc[j] = 0ull;
            const float* qrow = g_qpn + (size_t)q*HID;
            #pragma unroll
            for (int ck = 0; ck < 8; ck++) {
                int k0 = ck*32;
                u64 qv[16];
                #pragma unroll
                for (int i = 0; i < 4; i++) {
                    ulonglong2 p = *(const ulonglong2*)(qrow + k0 + i*8);
                    ulonglong2 p2 = *(const ulonglong2*)(qrow + k0 + i*8 + 4);
                    qv[i*4+0]=p.x; qv[i*4+1]=p.y; qv[i*4+2]=p2.x; qv[i*4+3]=p2.y;
                }
                #pragma unroll
                for (int j = 0; j < 6; j++) {
                    int rowIdx = rg*6 + j;
                    int gate = rowIdx >> 3, col = rowIdx & 7;
                    const float* wr = qWih + (size_t)(gate*256 + c0g + col)*HID + k0;
                    #pragma unroll
                    for (int i = 0; i < 4; i++) {
                        ulonglong2 p = *(const ulonglong2*)(wr + i*8);
                        ulonglong2 p2 = *(const ulonglong2*)(wr + i*8 + 4);
                        acc[j] = ffma2(qv[i*4+0], p.x, acc[j]);
                        acc[j] = ffma2(qv[i*4+1], p.y, acc[j]);
                        acc[j] = ffma2(qv[i*4+2], p2.x, acc[j]);
                        acc[j] = ffma2(qv[i*4+3], p2.y, acc[j]);
                    }
                }
            }
            #pragma unroll
            for (int j = 0; j < 6; j++)
                res[(rg*6 + j)*66 + q] = hsum2(acc[j]);
        }
        __syncthreads();
        if (tid < 256) {
            for (int o = tid; o < 512; o += 256) {
                int oq = o >> 3, col = o & 7;
                int c = c0g + col;
                float gr = res[(col)*66 + oq]      + qbih[c];
                float gz = res[(8+col)*66 + oq]    + qbih[256+c];
                float gn = res[(16+col)*66 + oq]   + qbih[512+c];
                float rv = sigf(gr + qbhh[c]);
                float zv = sigf(gz + qbhh[256+c]);
                float nv = tanhfast(gn + rv*qbhh[512+c]);
                out[oq*256 + c] = (1.f - zv)*nv;
            }
        }
    }
}

// ---------------- launch ------------------------------------------------------
extern "C" void kernel_launch(void* const* d_in, const int* in_sizes, int n_in,
                              void* d_out, int out_size) {
    const int*   qt   = (const int*)d_in[0];
    const int*   pt   = (const int*)d_in[1];
    const int*   nt   = (const int*)d_in[2];
    const float* temb = (const float*)d_in[3];
    const float* tWih = (const float*)d_in[4];
    const float* tWhh = (const float*)d_in[5];
    const float* tbih = (const float*)d_in[6];
    const float* tbhh = (const float*)d_in[7];
    const float* demb = (const float*)d_in[8];
    const float* cWih = (const float*)d_in[9];
    const float* cWhh = (const float*)d_in[10];
    const float* cbih = (const float*)d_in[11];
    const float* cbhh = (const float*)d_in[12];
    const float* aWih = (const float*)d_in[13];
    const float* aWhh = (const float*)d_in[14];
    const float* abih = (const float*)d_in[15];
    const float* abhh = (const float*)d_in[16];
    const float* ptab = (const float*)d_in[17];
    const float* posW = (const float*)d_in[18];
    const float* posb = (const float*)d_in[19];
    const float* qWih = (const float*)d_in[20];
    const float* qbih = (const float*)d_in[22];
    const float* qbhh = (const float*)d_in[23];

    gi_gemm_k<<<120, 256>>>(qt, pt, nt, temb, demb,
                            tWih, tbih, cWih, cbih, aWih, abih);
    scan_k<<<128, 512>>>(tWhh, tbhh, cWhh, cbhh, aWhh, abhh,
                         ptab, posW, posb, qWih, qbih, qbhh, (float*)d_out);
}

// round 12
// speedup vs baseline: 1.0797x; 1.0797x over previous
#include <cuda_runtime.h>
#include <math.h>

#define HID 256
#define QN 64
#define LQ 20
#define DN 24
#define LD 50
#define QROWS (QN*LQ)   // 1280
#define DROWS (DN*LD)   // 1200

typedef unsigned long long u64;

__device__ __forceinline__ u64 ffma2(u64 a, u64 b, u64 c) {
    u64 d; asm("fma.rn.f32x2 %0, %1, %2, %3;" : "=l"(d) : "l"(a), "l"(b), "l"(c)); return d;
}
__device__ __forceinline__ float hsum2(u64 s) {
    float lo, hi; asm("mov.b64 {%0, %1}, %2;" : "=f"(lo), "=f"(hi) : "l"(s)); return lo + hi;
}
__device__ __forceinline__ void unpack2(u64 s, float& lo, float& hi) {
    asm("mov.b64 {%0, %1}, %2;" : "=f"(lo), "=f"(hi) : "l"(s));
}
__device__ __forceinline__ u64 dupf(float v) {
    u64 d; asm("mov.b64 %0, {%1, %1};" : "=l"(d) : "f"(v)); return d;
}
__device__ __forceinline__ float dot4(float4 a, float4 b, float s) {
    s = fmaf(a.x, b.x, s); s = fmaf(a.y, b.y, s);
    s = fmaf(a.z, b.z, s); s = fmaf(a.w, b.w, s);
    return s;
}
__device__ __forceinline__ float sigf(float x) {
    return __fdividef(1.f, 1.f + __expf(-x));
}
__device__ __forceinline__ float tanhfast(float x) {
    return 1.f - __fdividef(2.f, __expf(2.f*x) + 1.f);
}
// atomic 8-byte tagged-pair exchange (value, step-tag)
__device__ __forceinline__ float2 ldp(const float2* p) {
    u64 r; asm volatile("ld.relaxed.gpu.global.b64 %0, [%1];" : "=l"(r) : "l"(p));
    float2 v; asm("mov.b64 {%0, %1}, %2;" : "=f"(v.x), "=f"(v.y) : "l"(r));
    return v;
}
__device__ __forceinline__ void stp(float2* p, float x, float y) {
    u64 r; asm("mov.b64 %0, {%1, %2};" : "=l"(r) : "f"(x), "f"(y));
    asm volatile("st.relaxed.gpu.global.b64 [%0], %1;" :: "l"(p), "l"(r));
}

// ---------------- scratch ----------------------------------------------------
__device__ __align__(16) float g_giq[QROWS*768];
__device__ __align__(16) float g_gic[DROWS*768];
__device__ __align__(16) float g_gia[DROWS*768];
__device__ __align__(16) float2 g_xd[2][2][24][256];  // [parity][chain][doc][col]
__device__ __align__(16) float2 g_xq[2][64][256];     // query h exchange
__device__ __align__(16) float g_hcf[DN*HID];
__device__ __align__(16) float g_haf[DN*HID];
__device__ __align__(16) float g_hqf[QN*HID];
__device__ __align__(16) float g_cfin[DN*HID];
__device__ __align__(16) float g_qpn[QN*HID];
__device__ __align__(16) unsigned g_bar[512];

// ---------------- K1: gi = emb[tok] @ W^T + b, gather fused, f32x2 -----------
#define GBM 128
#define GBN 192
#define GBK 32
#define ASD 132
#define BSD 196

__global__ void __launch_bounds__(256) gi_gemm_k(
    const int* __restrict__ qt, const int* __restrict__ pt, const int* __restrict__ nt,
    const float* __restrict__ temb, const float* __restrict__ demb,
    const float* __restrict__ tW, const float* __restrict__ tb,
    const float* __restrict__ cW, const float* __restrict__ cb,
    const float* __restrict__ aW, const float* __restrict__ ab) {
    __shared__ float As[GBK*ASD];
    __shared__ float Bs[GBK*BSD];
    __shared__ int toks[GBM];

    int bid = blockIdx.x;
    int tid = threadIdx.x;
    // reset exchange buffers (tag=0, value=0 == h0) and tail barriers each replay
    {
        int gz = bid*256 + tid;
        if (gz < 12288)       ((float4*)g_xd)[gz] = make_float4(0.f,0.f,0.f,0.f);
        else if (gz < 28672)  ((float4*)g_xq)[gz - 12288] = make_float4(0.f,0.f,0.f,0.f);
        if (bid == 0 && tid < 128)
            ((float4*)g_bar)[tid] = make_float4(0.f,0.f,0.f,0.f);
    }

    int seg = bid / 40;          // 0=query, 1=doc-c, 2=doc-a
    int rem = bid - seg*40;
    int mtl = rem >> 2, ntl = rem & 3;
    int m0 = mtl*GBM, n0 = ntl*GBN;

    const float* W; const float* bias; float* C; const float* emb; int M;
    if (seg == 0)      { W=tW; bias=tb; C=g_giq; emb=temb; M=QROWS; }
    else if (seg == 1) { W=cW; bias=cb; C=g_gic; emb=demb; M=DROWS; }
    else               { W=aW; bias=ab; C=g_gia; emb=demb; M=DROWS; }

    if (tid < GBM) {
        int m = m0 + tid;
        int tk = 0;
        if (m < M) {
            if (seg == 0) tk = qt[m];
            else tk = (m < 600) ? pt[m] : nt[m-600];
        }
        toks[tid] = tk;
    }
    __syncthreads();

    int tx = tid & 15, ty = tid >> 4;
    u64 acc2[4][12];
    #pragma unroll
    for (int p = 0; p < 4; p++)
        #pragma unroll
        for (int j = 0; j < 12; j++) acc2[p][j] = 0ull;

    for (int k0 = 0; k0 < HID; k0 += GBK) {
        #pragma unroll
        for (int q = 0; q < 4; q++) {
            int idx = q*256 + tid;
            int kq = idx >> 7, m = idx & 127;
            float4 v = make_float4(0.f,0.f,0.f,0.f);
            if (m0 + m < M) v = *(const float4*)(emb + (size_t)toks[m]*HID + k0 + kq*4);
            As[(kq*4+0)*ASD + m] = v.x; As[(kq*4+1)*ASD + m] = v.y;
            As[(kq*4+2)*ASD + m] = v.z; As[(kq*4+3)*ASD + m] = v.w;
        }
        #pragma unroll
        for (int q = 0; q < 6; q++) {
            int idx = q*256 + tid;
            int kq = idx / 192, n = idx - kq*192;
            float4 v = *(const float4*)(W + (size_t)(n0+n)*HID + k0 + kq*4);
            Bs[(kq*4+0)*BSD + n] = v.x; Bs[(kq*4+1)*BSD + n] = v.y;
            Bs[(kq*4+2)*BSD + n] = v.z; Bs[(kq*4+3)*BSD + n] = v.w;
        }
        __syncthreads();
        #pragma unroll 8
        for (int k = 0; k < GBK; k++) {
            ulonglong2 A01 = *(const ulonglong2*)(As + k*ASD + ty*8);
            ulonglong2 A23 = *(const ulonglong2*)(As + k*ASD + ty*8 + 4);
            u64 a2[4] = {A01.x, A01.y, A23.x, A23.y};
            float4 b0 = *(const float4*)(Bs + k*BSD + tx*4);
            float4 b1 = *(const float4*)(Bs + k*BSD + 64 + tx*4);
            float4 b2 = *(const float4*)(Bs + k*BSD + 128 + tx*4);
            u64 bb[12];
            bb[0]=dupf(b0.x); bb[1]=dupf(b0.y); bb[2]=dupf(b0.z); bb[3]=dupf(b0.w);
            bb[4]=dupf(b1.x); bb[5]=dupf(b1.y); bb[6]=dupf(b1.z); bb[7]=dupf(b1.w);
            bb[8]=dupf(b2.x); bb[9]=dupf(b2.y); bb[10]=dupf(b2.z); bb[11]=dupf(b2.w);
            #pragma unroll
            for (int p = 0; p < 4; p++)
                #pragma unroll
                for (int j = 0; j < 12; j++)
                    acc2[p][j] = ffma2(a2[p], bb[j], acc2[p][j]);
        }
        __syncthreads();
    }

    float4 bv[3];
    #pragma unroll
    for (int g = 0; g < 3; g++)
        bv[g] = *(const float4*)(bias + n0 + g*64 + tx*4);
    #pragma unroll
    for (int p = 0; p < 4; p++) {
        float vlo[12], vhi[12];
        #pragma unroll
        for (int j = 0; j < 12; j++) unpack2(acc2[p][j], vlo[j], vhi[j]);
        #pragma unroll
        for (int e = 0; e < 2; e++) {
            int m = m0 + ty*8 + p*2 + e;
            if (m >= M) continue;
            const float* vv = e ? vhi : vlo;
            #pragma unroll
            for (int g = 0; g < 3; g++) {
                float4 o;
                o.x = vv[g*4+0] + (&bv[g].x)[0];
                o.y = vv[g*4+1] + (&bv[g].x)[1];
                o.z = vv[g*4+2] + (&bv[g].x)[2];
                o.w = vv[g*4+3] + (&bv[g].x)[3];
                *(float4*)(C + (size_t)m*768 + n0 + g*64 + tx*4) = o;
            }
        }
    }
}

// ---------------- K2: GRU scans (tagged pairs, chain-split docs) + tail ------
__device__ __forceinline__ void bar_arrive_wait(unsigned* p, unsigned need) {
    asm volatile("red.release.gpu.global.add.u32 [%0], %1;" :: "l"(p), "r"(1u) : "memory");
    unsigned v;
    do {
        asm volatile("ld.acquire.gpu.global.u32 %0, [%1];" : "=r"(v) : "l"(p) : "memory");
    } while (v < need);
}

__global__ void __launch_bounds__(512) scan_k(
    const float* __restrict__ tWhh, const float* __restrict__ tbhh,
    const float* __restrict__ cWhh, const float* __restrict__ cbhh,
    const float* __restrict__ aWhh, const float* __restrict__ abhh,
    const float* __restrict__ ptab, const float* __restrict__ posW,
    const float* __restrict__ posb,
    const float* __restrict__ qWih, const float* __restrict__ qbih,
    const float* __restrict__ qbhh, float* __restrict__ out) {
    __shared__ __align__(16) float pool[6240];   // hs(4096)+parts(1632); tail reuses
    float* hs = pool;
    float* parts = pool + 4096;

    int bid = blockIdx.x, tid = threadIdx.x;
    bool isQ = (bid >= 96);
    int lane = tid & 31;
    int r = lane & 7, ks = lane >> 3;
    int row = (tid >> 5)*8 + r;
    bool act = tid < 384;

    // doc: 12 groups of 8 CTAs (docgrp 0..5 x chain 0..1), 4 docs each, c0 span 32
    // qry: 4 groups of 8 CTAs, 16 queries each, c0 span 32
    int bg = 0, c0, T, docgrp = 0, chain = 0;
    if (!isQ) {
        int g2 = bid >> 3;             // 0..11
        docgrp = g2 >> 1; chain = g2 & 1;
        c0 = (bid & 7) << 5; T = LD;
    } else {
        int qg = bid - 96; bg = qg >> 3; c0 = (qg & 7) << 5; T = LQ;
    }

    // ---- W slice into registers (rotated chunks, conflict-free h LDS) -------
    u64 wreg[32];
    if (act) {
        const float* Wp;
        if (!isQ) Wp = chain ? aWhh : cWhh;
        else      Wp = tWhh;
        int grow = (row >> 5)*256 + c0 + (row & 31);
        const float* base = Wp + (size_t)grow*HID + ks*64;
        #pragma unroll
        for (int i = 0; i < 8; i++) {
            int ch = (i + ks) & 7;
            ulonglong2 p0 = *(const ulonglong2*)(base + ch*8);
            ulonglong2 p1 = *(const ulonglong2*)(base + ch*8 + 4);
            wreg[i*4+0]=p0.x; wreg[i*4+1]=p0.y; wreg[i*4+2]=p1.x; wreg[i*4+3]=p1.y;
        }
    }

    // ---- phase-2 (producer) setup -------------------------------------------
    bool oact; int prI=0, pzI=0, pnI=0, hpI=0, hoff=0, cc=0, prow=0;
    float br=0.f, bz=0.f, bn=0.f;
    const float* giBase = nullptr;
    if (!isQ) {
        oact = (tid < 128);
        if (oact) {
            int b = tid >> 5, cl = tid & 31;
            cc = c0 + cl;
            prI = cl*5 + b; pzI = (32+cl)*5 + b; pnI = (64+cl)*5 + b;
            hpI = b*256 + cc;
            const float* bh = chain ? abhh : cbhh;
            br = bh[cc]; bz = bh[256+cc]; bn = bh[512+cc];
            giBase = (chain ? g_gia : g_gic) + (size_t)(docgrp*4 + b)*LD*768;
            hoff = (docgrp*4 + b)*256 + cc;
            prow = docgrp*4 + b;
        }
    } else {
        oact = true;
        int b = tid >> 5, cl = tid & 31;
        cc = c0 + cl;
        prI = cl*17 + b; pzI = (32+cl)*17 + b; pnI = (64+cl)*17 + b;
        hpI = b*256 + cc;
        br = tbhh[cc]; bz = tbhh[256+cc]; bn = tbhh[512+cc];
        giBase = g_giq + (size_t)(bg*16 + b)*LQ*768;
        hoff = (bg*16 + b)*256 + cc;
        prow = bg*16 + b;
    }

    for (int t = 0; t < T; t++) {
        int cur = t & 1;
        // gi prefetch (independent of h)
        float xr=0.f, xz=0.f, xn=0.f;
        if (oact) {
            const float* gp = giBase + (size_t)t*768;
            xr = gp[cc]; xz = gp[256+cc]; xn = gp[512+cc];
        }
        // ---- stage h(t): poll tagged pairs into smem ----
        float tgt = (float)t;
        if (!isQ) {
            int p0 = tid*2;
            int lrow = p0 >> 8, scol = p0 & 255;        // doc 0..3, col
            const float2* sp = &g_xd[cur][chain][docgrp*4 + lrow][scol];
            float2 v0, v1;
            do { v0 = ldp(sp); v1 = ldp(sp+1); } while (v0.y != tgt || v1.y != tgt);
            *(float2*)(hs + lrow*256 + scol) = make_float2(v0.x, v1.x);
        } else {
            int p0 = tid*8;
            int lrow = p0 >> 8, scol = p0 & 255;
            const float2* sp = &g_xq[cur][bg*16 + lrow][scol];
            float2 v[8]; bool ok;
            do {
                #pragma unroll
                for (int i = 0; i < 8; i++) v[i] = ldp(sp + i);
                ok = true;
                #pragma unroll
                for (int i = 0; i < 8; i++) ok &= (v[i].y == tgt);
            } while (!ok);
            *(float4*)(hs + lrow*256 + scol)     = make_float4(v[0].x, v[1].x, v[2].x, v[3].x);
            *(float4*)(hs + lrow*256 + scol + 4) = make_float4(v[4].x, v[5].x, v[6].x, v[7].x);
        }
        __syncthreads();
        // ---- phase 1: gh partials, W in regs, h from smem ----
        if (act) {
            if (!isQ) {
                u64 acc[4];
                #pragma unroll
                for (int b = 0; b < 4; b++) acc[b] = 0ull;
                #pragma unroll
                for (int i = 0; i < 8; i++) {
                    int off = ((i + ks) & 7) * 8 + ks*64;
                    #pragma unroll
                    for (int b = 0; b < 4; b++) {
                        const float* hp = hs + b*256 + off;
                        ulonglong2 h0 = *(const ulonglong2*)hp;
                        ulonglong2 h1 = *(const ulonglong2*)(hp + 4);
                        acc[b] = ffma2(h0.x, wreg[i*4+0], acc[b]);
                        acc[b] = ffma2(h0.y, wreg[i*4+1], acc[b]);
                        acc[b] = ffma2(h1.x, wreg[i*4+2], acc[b]);
                        acc[b] = ffma2(h1.y, wreg[i*4+3], acc[b]);
                    }
                }
                #pragma unroll
                for (int b = 0; b < 4; b++) {
                    float s = hsum2(acc[b]);
                    s += __shfl_xor_sync(0xffffffffu, s, 8);
                    s += __shfl_xor_sync(0xffffffffu, s, 16);
                    if (ks == 0) parts[row*5 + b] = s;
                }
            } else {
                #pragma unroll
                for (int half = 0; half < 2; half++) {
                    u64 acc[8];
                    #pragma unroll
                    for (int b = 0; b < 8; b++) acc[b] = 0ull;
                    #pragma unroll
                    for (int i = 0; i < 8; i++) {
                        int off = ((i + ks) & 7) * 8 + ks*64;
                        #pragma unroll
                        for (int b = 0; b < 8; b++) {
                            const float* hp = hs + (half*8 + b)*256 + off;
                            ulonglong2 h0 = *(const ulonglong2*)hp;
                            ulonglong2 h1 = *(const ulonglong2*)(hp + 4);
                            acc[b] = ffma2(h0.x, wreg[i*4+0], acc[b]);
                            acc[b] = ffma2(h0.y, wreg[i*4+1], acc[b]);
                            acc[b] = ffma2(h1.x, wreg[i*4+2], acc[b]);
                            acc[b] = ffma2(h1.y, wreg[i*4+3], acc[b]);
                        }
                    }
                    #pragma unroll
                    for (int b = 0; b < 8; b++) {
                        float s = hsum2(acc[b]);
                        s += __shfl_xor_sync(0xffffffffu, s, 8);
                        s += __shfl_xor_sync(0xffffffffu, s, 16);
                        if (ks == 0) parts[row*17 + half*8 + b] = s;
                    }
                }
            }
        }
        __syncthreads();
        // ---- phase 2: gate math, publish tagged pair ----
        if (oact) {
            float ghr = br + parts[prI];
            float ghz = bz + parts[pzI];
            float ghn = bn + parts[pnI];
            float rr2 = sigf(xr + ghr);
            float zz = sigf(xz + ghz);
            float nn = tanhfast(xn + rr2*ghn);
            float hv = (1.f - zz)*nn + zz*hs[hpI];
            if (t + 1 < T) {
                float2* dp = (!isQ) ? &g_xd[(t+1)&1][chain][prow][cc]
                                    : &g_xq[(t+1)&1][prow][cc];
                stp(dp, hv, (float)(t+1));
            } else {
                if (!isQ) (chain ? g_haf : g_hcf)[hoff] = hv;
                else      g_hqf[hoff] = hv;
            }
        }
        // no extra barrier: next step's poll is the barrier
    }

    // ================= fused tail =================
    __syncthreads();
    if (tid == 0) bar_arrive_wait(g_bar + 500, 128);
    __syncthreads();

    if (bid < 8) {
        float* in_s = pool;
        int c0p = bid * 32;
        for (int i = tid; i < 24*260; i += 512) {
            int d = i / 260, k = i - d*260;
            in_s[i] = (k < 256) ? g_hcf[d*256 + k] : ptab[(d % 12)*4 + (k - 256)];
        }
        __syncthreads();
        if (tid < 256) {
            int kg = tid & 7, cx = tid >> 3;
            int c = c0p + cx;
            int k0 = kg*33, k1 = (kg == 7) ? 260 : k0 + 33;
            float accp[24];
            #pragma unroll
            for (int d = 0; d < 24; d++) accp[d] = 0.f;
            const float* wr = posW + (size_t)c*260;
            for (int k = k0; k < k1; k++) {
                float wv = wr[k];
                #pragma unroll
                for (int d = 0; d < 24; d++) accp[d] = fmaf(wv, in_s[d*260 + k], accp[d]);
            }
            #pragma unroll
            for (int d = 0; d < 24; d++) {
                float s = accp[d];
                s += __shfl_xor_sync(0xffffffffu, s, 1);
                s += __shfl_xor_sync(0xffffffffu, s, 2);
                s += __shfl_xor_sync(0xffffffffu, s, 4);
                if (kg == 0) g_cfin[d*256 + c] = s + posb[c];
            }
        }
    } else if (bid < 72) {
        int q = bid - 8;
        float* enc = pool;
        float* wgt = pool + 256;
        if (tid < 256) enc[tid] = g_hqf[q*256 + tid];
        __syncthreads();
        if (tid < 192) {
            int d = tid >> 3, sg = tid & 7;
            const float4* ar = (const float4*)(g_haf + d*256 + sg*32);
            const float4* er = (const float4*)(enc + sg*32);
            float s = 0.f;
            #pragma unroll
            for (int i = 0; i < 8; i++) s = dot4(er[i], ar[i], s);
            s += __shfl_xor_sync(0xffffffffu, s, 1);
            s += __shfl_xor_sync(0xffffffffu, s, 2);
            s += __shfl_xor_sync(0xffffffffu, s, 4);
            if (sg == 0) wgt[d] = s;
        }
        __syncthreads();
        if (tid < 2) {
            int off = tid*12;
            float mx = -1e30f;
            for (int d = 0; d < 12; d++) mx = fmaxf(mx, wgt[off+d]);
            float sum = 0.f;
            for (int d = 0; d < 12; d++) { float e = __expf(wgt[off+d]-mx); wgt[off+d]=e; sum += e; }
            float inv = __fdividef(1.f, sum);
            for (int d = 0; d < 12; d++) wgt[off+d] *= inv;
        }
    }
    __syncthreads();
    if (tid == 0) bar_arrive_wait(g_bar + 501, 128);
    __syncthreads();

    if (bid >= 8 && bid < 72 && tid < 256) {
        int q = bid - 8;
        float* enc = pool;
        float* wgt = pool + 256;
        float v = enc[tid];
        #pragma unroll
        for (int d = 0; d < 24; d++) v = fmaf(wgt[d], g_cfin[d*256 + tid], v);
        g_qpn[q*256 + tid] = v;
    }
    __syncthreads();
    if (tid == 0) bar_arrive_wait(g_bar + 502, 128);
    __syncthreads();

    if (bid < 32) {
        float* res = pool;
        int c0g = bid * 8;
        if (tid < 256) {
            int w = tid >> 5, ln = tid & 31;
            int q = (w & 1)*32 + ln;
            int rg = w >> 1;
            u64 acc[6];
            #pragma unroll
            for (int j = 0; j < 6; j++) acc[j] = 0ull;
            const float* qrow = g_qpn + (size_t)q*HID;
            #pragma unroll
            for (int ck = 0; ck < 8; ck++) {
                int k0 = ck*32;
                u64 qv[16];
                #pragma unroll
                for (int i = 0; i < 4; i++) {
                    ulonglong2 p = *(const ulonglong2*)(qrow + k0 + i*8);
                    ulonglong2 p2 = *(const ulonglong2*)(qrow + k0 + i*8 + 4);
                    qv[i*4+0]=p.x; qv[i*4+1]=p.y; qv[i*4+2]=p2.x; qv[i*4+3]=p2.y;
                }
                #pragma unroll
                for (int j = 0; j < 6; j++) {
                    int rowIdx = rg*6 + j;
                    int gate = rowIdx >> 3, col = rowIdx & 7;
                    const float* wr = qWih + (size_t)(gate*256 + c0g + col)*HID + k0;
                    #pragma unroll
                    for (int i = 0; i < 4; i++) {
                        ulonglong2 p = *(const ulonglong2*)(wr + i*8);
                        ulonglong2 p2 = *(const ulonglong2*)(wr + i*8 + 4);
                        acc[j] = ffma2(qv[i*4+0], p.x, acc[j]);
                        acc[j] = ffma2(qv[i*4+1], p.y, acc[j]);
                        acc[j] = ffma2(qv[i*4+2], p2.x, acc[j]);
                        acc[j] = ffma2(qv[i*4+3], p2.y, acc[j]);
                    }
                }
            }
            #pragma unroll
            for (int j = 0; j < 6; j++)
                res[(rg*6 + j)*66 + q] = hsum2(acc[j]);
        }
        __syncthreads();
        if (tid < 256) {
            for (int o = tid; o < 512; o += 256) {
                int oq = o >> 3, col = o & 7;
                int c = c0g + col;
                float gr = res[(col)*66 + oq]      + qbih[c];
                float gz = res[(8+col)*66 + oq]    + qbih[256+c];
                float gn = res[(16+col)*66 + oq]   + qbih[512+c];
                float rv = sigf(gr + qbhh[c]);
                float zv = sigf(gz + qbhh[256+c]);
                float nv = tanhfast(gn + rv*qbhh[512+c]);
                out[oq*256 + c] = (1.f - zv)*nv;
            }
        }
    }
}

// ---------------- launch ------------------------------------------------------
extern "C" void kernel_launch(void* const* d_in, const int* in_sizes, int n_in,
                              void* d_out, int out_size) {
    const int*   qt   = (const int*)d_in[0];
    const int*   pt   = (const int*)d_in[1];
    const int*   nt   = (const int*)d_in[2];
    const float* temb = (const float*)d_in[3];
    const float* tWih = (const float*)d_in[4];
    const float* tWhh = (const float*)d_in[5];
    const float* tbih = (const float*)d_in[6];
    const float* tbhh = (const float*)d_in[7];
    const float* demb = (const float*)d_in[8];
    const float* cWih = (const float*)d_in[9];
    const float* cWhh = (const float*)d_in[10];
    const float* cbih = (const float*)d_in[11];
    const float* cbhh = (const float*)d_in[12];
    const float* aWih = (const float*)d_in[13];
    const float* aWhh = (const float*)d_in[14];
    const float* abih = (const float*)d_in[15];
    const float* abhh = (const float*)d_in[16];
    const float* ptab = (const float*)d_in[17];
    const float* posW = (const float*)d_in[18];
    const float* posb = (const float*)d_in[19];
    const float* qWih = (const float*)d_in[20];
    const float* qbih = (const float*)d_in[22];
    const float* qbhh = (const float*)d_in[23];

    gi_gemm_k<<<120, 256>>>(qt, pt, nt, temb, demb,
                            tWih, tbih, cWih, cbih, aWih, abih);
    scan_k<<<128, 512>>>(tWhh, tbhh, cWhh, cbhh, aWhh, abhh,
                         ptab, posW, posb, qWih, qbih, qbhh, (float*)d_out);
}

// round 13
// speedup vs baseline: 1.1615x; 1.0758x over previous
#include <cuda_runtime.h>
#include <math.h>

#define HID 256
#define QN 64
#define LQ 20
#define DN 24
#define LD 50
#define QROWS (QN*LQ)   // 1280
#define DROWS (DN*LD)   // 1200

// scan smem layout (floats): hs[4096] | parts[1632] | gi_s[30720]
#define HS_OFF 0
#define PARTS_OFF 4096
#define GIS_OFF 5728
#define SMEMF (GIS_OFF + 30720)           // 36448 floats = 145792 B

typedef unsigned long long u64;

__device__ __forceinline__ u64 ffma2(u64 a, u64 b, u64 c) {
    u64 d; asm("fma.rn.f32x2 %0, %1, %2, %3;" : "=l"(d) : "l"(a), "l"(b), "l"(c)); return d;
}
__device__ __forceinline__ float hsum2(u64 s) {
    float lo, hi; asm("mov.b64 {%0, %1}, %2;" : "=f"(lo), "=f"(hi) : "l"(s)); return lo + hi;
}
__device__ __forceinline__ void unpack2(u64 s, float& lo, float& hi) {
    asm("mov.b64 {%0, %1}, %2;" : "=f"(lo), "=f"(hi) : "l"(s));
}
__device__ __forceinline__ u64 dupf(float v) {
    u64 d; asm("mov.b64 %0, {%1, %1};" : "=l"(d) : "f"(v)); return d;
}
__device__ __forceinline__ float dot4(float4 a, float4 b, float s) {
    s = fmaf(a.x, b.x, s); s = fmaf(a.y, b.y, s);
    s = fmaf(a.z, b.z, s); s = fmaf(a.w, b.w, s);
    return s;
}
__device__ __forceinline__ float sigf(float x) {
    return __fdividef(1.f, 1.f + __expf(-x));
}
__device__ __forceinline__ float tanhfast(float x) {
    return 1.f - __fdividef(2.f, __expf(2.f*x) + 1.f);
}
// atomic 8-byte tagged-pair exchange (value, step-tag)
__device__ __forceinline__ float2 ldp(const float2* p) {
    u64 r; asm volatile("ld.relaxed.gpu.global.b64 %0, [%1];" : "=l"(r) : "l"(p));
    float2 v; asm("mov.b64 {%0, %1}, %2;" : "=f"(v.x), "=f"(v.y) : "l"(r));
    return v;
}
__device__ __forceinline__ void stp(float2* p, float x, float y) {
    u64 r; asm("mov.b64 %0, {%1, %2};" : "=l"(r) : "f"(x), "f"(y));
    asm volatile("st.relaxed.gpu.global.b64 [%0], %1;" :: "l"(p), "l"(r));
}

// ---------------- scratch ----------------------------------------------------
__device__ __align__(16) float g_giq[QROWS*768];
__device__ __align__(16) float g_gic[DROWS*768];
__device__ __align__(16) float g_gia[DROWS*768];
__device__ __align__(16) float2 g_xd[2][2][24][256];  // [parity][chain][doc][col]
__device__ __align__(16) float2 g_xq[2][64][256];     // query h exchange
__device__ __align__(16) float g_hcf[DN*HID];
__device__ __align__(16) float g_haf[DN*HID];
__device__ __align__(16) float g_hqf[QN*HID];
__device__ __align__(16) float g_cfin[DN*HID];
__device__ __align__(16) float g_qpn[QN*HID];
__device__ __align__(16) unsigned g_bar[512];

// ---------------- K1: gi = emb[tok] @ W^T + b, gather fused, f32x2 -----------
#define GBM 128
#define GBN 192
#define GBK 32
#define ASD 132
#define BSD 196

__global__ void __launch_bounds__(256) gi_gemm_k(
    const int* __restrict__ qt, const int* __restrict__ pt, const int* __restrict__ nt,
    const float* __restrict__ temb, const float* __restrict__ demb,
    const float* __restrict__ tW, const float* __restrict__ tb,
    const float* __restrict__ cW, const float* __restrict__ cb,
    const float* __restrict__ aW, const float* __restrict__ ab) {
    __shared__ float As[GBK*ASD];
    __shared__ float Bs[GBK*BSD];
    __shared__ int toks[GBM];

    int bid = blockIdx.x;
    int tid = threadIdx.x;
    // reset exchange buffers (tag=0, value=0 == h0) and tail barriers each replay
    {
        int gz = bid*256 + tid;
        if (gz < 12288)       ((float4*)g_xd)[gz] = make_float4(0.f,0.f,0.f,0.f);
        else if (gz < 28672)  ((float4*)g_xq)[gz - 12288] = make_float4(0.f,0.f,0.f,0.f);
        if (bid == 0 && tid < 128)
            ((float4*)g_bar)[tid] = make_float4(0.f,0.f,0.f,0.f);
    }

    int seg = bid / 40;          // 0=query, 1=doc-c, 2=doc-a
    int rem = bid - seg*40;
    int mtl = rem >> 2, ntl = rem & 3;
    int m0 = mtl*GBM, n0 = ntl*GBN;

    const float* W; const float* bias; float* C; const float* emb; int M;
    if (seg == 0)      { W=tW; bias=tb; C=g_giq; emb=temb; M=QROWS; }
    else if (seg == 1) { W=cW; bias=cb; C=g_gic; emb=demb; M=DROWS; }
    else               { W=aW; bias=ab; C=g_gia; emb=demb; M=DROWS; }

    if (tid < GBM) {
        int m = m0 + tid;
        int tk = 0;
        if (m < M) {
            if (seg == 0) tk = qt[m];
            else tk = (m < 600) ? pt[m] : nt[m-600];
        }
        toks[tid] = tk;
    }
    __syncthreads();

    int tx = tid & 15, ty = tid >> 4;
    u64 acc2[4][12];
    #pragma unroll
    for (int p = 0; p < 4; p++)
        #pragma unroll
        for (int j = 0; j < 12; j++) acc2[p][j] = 0ull;

    for (int k0 = 0; k0 < HID; k0 += GBK) {
        #pragma unroll
        for (int q = 0; q < 4; q++) {
            int idx = q*256 + tid;
            int kq = idx >> 7, m = idx & 127;
            float4 v = make_float4(0.f,0.f,0.f,0.f);
            if (m0 + m < M) v = *(const float4*)(emb + (size_t)toks[m]*HID + k0 + kq*4);
            As[(kq*4+0)*ASD + m] = v.x; As[(kq*4+1)*ASD + m] = v.y;
            As[(kq*4+2)*ASD + m] = v.z; As[(kq*4+3)*ASD + m] = v.w;
        }
        #pragma unroll
        for (int q = 0; q < 6; q++) {
            int idx = q*256 + tid;
            int kq = idx / 192, n = idx - kq*192;
            float4 v = *(const float4*)(W + (size_t)(n0+n)*HID + k0 + kq*4);
            Bs[(kq*4+0)*BSD + n] = v.x; Bs[(kq*4+1)*BSD + n] = v.y;
            Bs[(kq*4+2)*BSD + n] = v.z; Bs[(kq*4+3)*BSD + n] = v.w;
        }
        __syncthreads();
        #pragma unroll 8
        for (int k = 0; k < GBK; k++) {
            ulonglong2 A01 = *(const ulonglong2*)(As + k*ASD + ty*8);
            ulonglong2 A23 = *(const ulonglong2*)(As + k*ASD + ty*8 + 4);
            u64 a2[4] = {A01.x, A01.y, A23.x, A23.y};
            float4 b0 = *(const float4*)(Bs + k*BSD + tx*4);
            float4 b1 = *(const float4*)(Bs + k*BSD + 64 + tx*4);
            float4 b2 = *(const float4*)(Bs + k*BSD + 128 + tx*4);
            u64 bb[12];
            bb[0]=dupf(b0.x); bb[1]=dupf(b0.y); bb[2]=dupf(b0.z); bb[3]=dupf(b0.w);
            bb[4]=dupf(b1.x); bb[5]=dupf(b1.y); bb[6]=dupf(b1.z); bb[7]=dupf(b1.w);
            bb[8]=dupf(b2.x); bb[9]=dupf(b2.y); bb[10]=dupf(b2.z); bb[11]=dupf(b2.w);
            #pragma unroll
            for (int p = 0; p < 4; p++)
                #pragma unroll
                for (int j = 0; j < 12; j++)
                    acc2[p][j] = ffma2(a2[p], bb[j], acc2[p][j]);
        }
        __syncthreads();
    }

    float4 bv[3];
    #pragma unroll
    for (int g = 0; g < 3; g++)
        bv[g] = *(const float4*)(bias + n0 + g*64 + tx*4);
    #pragma unroll
    for (int p = 0; p < 4; p++) {
        float vlo[12], vhi[12];
        #pragma unroll
        for (int j = 0; j < 12; j++) unpack2(acc2[p][j], vlo[j], vhi[j]);
        #pragma unroll
        for (int e = 0; e < 2; e++) {
            int m = m0 + ty*8 + p*2 + e;
            if (m >= M) continue;
            const float* vv = e ? vhi : vlo;
            #pragma unroll
            for (int g = 0; g < 3; g++) {
                float4 o;
                o.x = vv[g*4+0] + (&bv[g].x)[0];
                o.y = vv[g*4+1] + (&bv[g].x)[1];
                o.z = vv[g*4+2] + (&bv[g].x)[2];
                o.w = vv[g*4+3] + (&bv[g].x)[3];
                *(float4*)(C + (size_t)m*768 + n0 + g*64 + tx*4) = o;
            }
        }
    }
}

// ---------------- K2: GRU scans (tagged pairs, gi in smem) + fused tail ------
__device__ __forceinline__ void bar_arrive_wait(unsigned* p, unsigned need) {
    asm volatile("red.release.gpu.global.add.u32 [%0], %1;" :: "l"(p), "r"(1u) : "memory");
    unsigned v;
    do {
        asm volatile("ld.acquire.gpu.global.u32 %0, [%1];" : "=r"(v) : "l"(p) : "memory");
    } while (v < need);
}

__global__ void __launch_bounds__(512) scan_k(
    const float* __restrict__ tWhh, const float* __restrict__ tbhh,
    const float* __restrict__ cWhh, const float* __restrict__ cbhh,
    const float* __restrict__ aWhh, const float* __restrict__ abhh,
    const float* __restrict__ ptab, const float* __restrict__ posW,
    const float* __restrict__ posb,
    const float* __restrict__ qWih, const float* __restrict__ qbih,
    const float* __restrict__ qbhh, float* __restrict__ out) {
    extern __shared__ __align__(16) float pool[];
    float* hs = pool + HS_OFF;
    float* parts = pool + PARTS_OFF;
    float* gi_s = pool + GIS_OFF;

    int bid = blockIdx.x, tid = threadIdx.x;
    bool isQ = (bid >= 96);
    int lane = tid & 31;
    int r = lane & 7, ks = lane >> 3;
    int row = (tid >> 5)*8 + r;
    bool act = tid < 384;

    // doc: 12 groups of 8 CTAs (docgrp 0..5 x chain 0..1), 4 docs each, c0 span 32
    // qry: 4 groups of 8 CTAs, 16 queries each, c0 span 32
    int bg = 0, c0, T, docgrp = 0, chain = 0;
    if (!isQ) {
        int g2 = bid >> 3;             // 0..11
        docgrp = g2 >> 1; chain = g2 & 1;
        c0 = (bid & 7) << 5; T = LD;
    } else {
        int qg = bid - 96; bg = qg >> 3; c0 = (qg & 7) << 5; T = LQ;
    }

    // ---- W slice into registers (rotated chunks, conflict-free h LDS) -------
    u64 wreg[32];
    if (act) {
        const float* Wp;
        if (!isQ) Wp = chain ? aWhh : cWhh;
        else      Wp = tWhh;
        int grow = (row >> 5)*256 + c0 + (row & 31);
        const float* base = Wp + (size_t)grow*HID + ks*64;
        #pragma unroll
        for (int i = 0; i < 8; i++) {
            int ch = (i + ks) & 7;
            ulonglong2 p0 = *(const ulonglong2*)(base + ch*8);
            ulonglong2 p1 = *(const ulonglong2*)(base + ch*8 + 4);
            wreg[i*4+0]=p0.x; wreg[i*4+1]=p0.y; wreg[i*4+2]=p1.x; wreg[i*4+3]=p1.y;
        }
    }

    // ---- stage the ENTIRE gi slice for this CTA into smem --------------------
    if (!isQ) {
        // 600 segments: [t 0..49][gate 0..2][b 0..3], 8 float4 each
        const float* gsrc = chain ? g_gia : g_gic;
        for (int idx = tid; idx < 4800; idx += 512) {
            int seg = idx >> 3, f4 = idx & 7;
            int t = seg / 12, rem2 = seg - t*12;
            int gate = rem2 >> 2, b = rem2 & 3;
            float4 v = *(const float4*)(gsrc + (size_t)(docgrp*4 + b)*(LD*768)
                                        + (size_t)t*768 + gate*256 + c0 + f4*4);
            *(float4*)(gi_s + t*384 + gate*128 + b*32 + f4*4) = v;
        }
    } else {
        // 960 segments: [t 0..19][gate 0..2][b 0..15], 8 float4 each
        for (int idx = tid; idx < 7680; idx += 512) {
            int seg = idx >> 3, f4 = idx & 7;
            int t = seg / 48, rem2 = seg - t*48;
            int gate = rem2 >> 4, b = rem2 & 15;
            float4 v = *(const float4*)(g_giq + (size_t)(bg*16 + b)*(LQ*768)
                                        + (size_t)t*768 + gate*256 + c0 + f4*4);
            *(float4*)(gi_s + t*1536 + gate*512 + b*32 + f4*4) = v;
        }
    }

    // ---- phase-2 (producer) setup -------------------------------------------
    bool oact; int prI=0, pzI=0, pnI=0, hpI=0, hoff=0, cc=0, prow=0, gbase=0;
    float br=0.f, bz=0.f, bn=0.f;
    if (!isQ) {
        oact = (tid < 128);
        if (oact) {
            int b = tid >> 5, cl = tid & 31;
            cc = c0 + cl;
            prI = cl*5 + b; pzI = (32+cl)*5 + b; pnI = (64+cl)*5 + b;
            hpI = b*256 + cc;
            const float* bh = chain ? abhh : cbhh;
            br = bh[cc]; bz = bh[256+cc]; bn = bh[512+cc];
            hoff = (docgrp*4 + b)*256 + cc;
            prow = docgrp*4 + b;
            gbase = b*32 + cl;           // gi_s: t*384 + gate*128 + gbase
        }
    } else {
        oact = true;
        int b = tid >> 5, cl = tid & 31;
        cc = c0 + cl;
        prI = cl*17 + b; pzI = (32+cl)*17 + b; pnI = (64+cl)*17 + b;
        hpI = b*256 + cc;
        br = tbhh[cc]; bz = tbhh[256+cc]; bn = tbhh[512+cc];
        hoff = (bg*16 + b)*256 + cc;
        prow = bg*16 + b;
        gbase = b*32 + cl;               // gi_s: t*1536 + gate*512 + gbase
    }

    for (int t = 0; t < T; t++) {
        int cur = t & 1;
        // ---- stage h(t): poll tagged pairs into smem ----
        float tgt = (float)t;
        if (!isQ) {
            int p0 = tid*2;
            int lrow = p0 >> 8, scol = p0 & 255;
            const float2* sp = &g_xd[cur][chain][docgrp*4 + lrow][scol];
            float2 v0, v1;
            do { v0 = ldp(sp); v1 = ldp(sp+1); } while (v0.y != tgt || v1.y != tgt);
            *(float2*)(hs + lrow*256 + scol) = make_float2(v0.x, v1.x);
        } else {
            int p0 = tid*8;
            int lrow = p0 >> 8, scol = p0 & 255;
            const float2* sp = &g_xq[cur][bg*16 + lrow][scol];
            float2 v[8]; bool ok;
            do {
                #pragma unroll
                for (int i = 0; i < 8; i++) v[i] = ldp(sp + i);
                ok = true;
                #pragma unroll
                for (int i = 0; i < 8; i++) ok &= (v[i].y == tgt);
            } while (!ok);
            *(float4*)(hs + lrow*256 + scol)     = make_float4(v[0].x, v[1].x, v[2].x, v[3].x);
            *(float4*)(hs + lrow*256 + scol + 4) = make_float4(v[4].x, v[5].x, v[6].x, v[7].x);
        }
        __syncthreads();
        // ---- phase 1: gh partials, W in regs, h from smem ----
        if (act) {
            if (!isQ) {
                u64 acc[4];
                #pragma unroll
                for (int b = 0; b < 4; b++) acc[b] = 0ull;
                #pragma unroll
                for (int i = 0; i < 8; i++) {
                    int off = ((i + ks) & 7) * 8 + ks*64;
                    #pragma unroll
                    for (int b = 0; b < 4; b++) {
                        const float* hp = hs + b*256 + off;
                        ulonglong2 h0 = *(const ulonglong2*)hp;
                        ulonglong2 h1 = *(const ulonglong2*)(hp + 4);
                        acc[b] = ffma2(h0.x, wreg[i*4+0], acc[b]);
                        acc[b] = ffma2(h0.y, wreg[i*4+1], acc[b]);
                        acc[b] = ffma2(h1.x, wreg[i*4+2], acc[b]);
                        acc[b] = ffma2(h1.y, wreg[i*4+3], acc[b]);
                    }
                }
                #pragma unroll
                for (int b = 0; b < 4; b++) {
                    float s = hsum2(acc[b]);
                    s += __shfl_xor_sync(0xffffffffu, s, 8);
                    s += __shfl_xor_sync(0xffffffffu, s, 16);
                    if (ks == 0) parts[row*5 + b] = s;
                }
            } else {
                #pragma unroll
                for (int half = 0; half < 2; half++) {
                    u64 acc[8];
                    #pragma unroll
                    for (int b = 0; b < 8; b++) acc[b] = 0ull;
                    #pragma unroll
                    for (int i = 0; i < 8; i++) {
                        int off = ((i + ks) & 7) * 8 + ks*64;
                        #pragma unroll
                        for (int b = 0; b < 8; b++) {
                            const float* hp = hs + (half*8 + b)*256 + off;
                            ulonglong2 h0 = *(const ulonglong2*)hp;
                            ulonglong2 h1 = *(const ulonglong2*)(hp + 4);
                            acc[b] = ffma2(h0.x, wreg[i*4+0], acc[b]);
                            acc[b] = ffma2(h0.y, wreg[i*4+1], acc[b]);
                            acc[b] = ffma2(h1.x, wreg[i*4+2], acc[b]);
                            acc[b] = ffma2(h1.y, wreg[i*4+3], acc[b]);
                        }
                    }
                    #pragma unroll
                    for (int b = 0; b < 8; b++) {
                        float s = hsum2(acc[b]);
                        s += __shfl_xor_sync(0xffffffffu, s, 8);
                        s += __shfl_xor_sync(0xffffffffu, s, 16);
                        if (ks == 0) parts[row*17 + half*8 + b] = s;
                    }
                }
            }
        }
        __syncthreads();
        // ---- phase 2: gate math (gi from smem), publish tagged pair ----
        if (oact) {
            float xr, xz, xn;
            if (!isQ) {
                const float* gp = gi_s + t*384 + gbase;
                xr = gp[0]; xz = gp[128]; xn = gp[256];
            } else {
                const float* gp = gi_s + t*1536 + gbase;
                xr = gp[0]; xz = gp[512]; xn = gp[1024];
            }
            float ghr = br + parts[prI];
            float ghz = bz + parts[pzI];
            float ghn = bn + parts[pnI];
            float rr2 = sigf(xr + ghr);
            float zz = sigf(xz + ghz);
            float nn = tanhfast(xn + rr2*ghn);
            float hv = (1.f - zz)*nn + zz*hs[hpI];
            if (t + 1 < T) {
                float2* dp = (!isQ) ? &g_xd[(t+1)&1][chain][prow][cc]
                                    : &g_xq[(t+1)&1][prow][cc];
                stp(dp, hv, (float)(t+1));
            } else {
                if (!isQ) (chain ? g_haf : g_hcf)[hoff] = hv;
                else      g_hqf[hoff] = hv;
            }
        }
        // no extra barrier: next step's poll is the barrier
    }

    // ================= fused tail =================
    __syncthreads();
    if (tid == 0) bar_arrive_wait(g_bar + 500, 128);
    __syncthreads();

    if (bid < 8) {
        float* in_s = pool;
        int c0p = bid * 32;
        for (int i = tid; i < 24*260; i += 512) {
            int d = i / 260, k = i - d*260;
            in_s[i] = (k < 256) ? g_hcf[d*256 + k] : ptab[(d % 12)*4 + (k - 256)];
        }
        __syncthreads();
        if (tid < 256) {
            int kg = tid & 7, cx = tid >> 3;
            int c = c0p + cx;
            int k0 = kg*33, k1 = (kg == 7) ? 260 : k0 + 33;
            float accp[24];
            #pragma unroll
            for (int d = 0; d < 24; d++) accp[d] = 0.f;
            const float* wr = posW + (size_t)c*260;
            for (int k = k0; k < k1; k++) {
                float wv = wr[k];
                #pragma unroll
                for (int d = 0; d < 24; d++) accp[d] = fmaf(wv, in_s[d*260 + k], accp[d]);
            }
            #pragma unroll
            for (int d = 0; d < 24; d++) {
                float s = accp[d];
                s += __shfl_xor_sync(0xffffffffu, s, 1);
                s += __shfl_xor_sync(0xffffffffu, s, 2);
                s += __shfl_xor_sync(0xffffffffu, s, 4);
                if (kg == 0) g_cfin[d*256 + c] = s + posb[c];
            }
        }
    } else if (bid < 72) {
        int q = bid - 8;
        float* enc = pool;
        float* wgt = pool + 256;
        if (tid < 256) enc[tid] = g_hqf[q*256 + tid];
        __syncthreads();
        if (tid < 192) {
            int d = tid >> 3, sg = tid & 7;
            const float4* ar = (const float4*)(g_haf + d*256 + sg*32);
            const float4* er = (const float4*)(enc + sg*32);
            float s = 0.f;
            #pragma unroll
            for (int i = 0; i < 8; i++) s = dot4(er[i], ar[i], s);
            s += __shfl_xor_sync(0xffffffffu, s, 1);
            s += __shfl_xor_sync(0xffffffffu, s, 2);
            s += __shfl_xor_sync(0xffffffffu, s, 4);
            if (sg == 0) wgt[d] = s;
        }
        __syncthreads();
        if (tid < 2) {
            int off = tid*12;
            float mx = -1e30f;
            for (int d = 0; d < 12; d++) mx = fmaxf(mx, wgt[off+d]);
            float sum = 0.f;
            for (int d = 0; d < 12; d++) { float e = __expf(wgt[off+d]-mx); wgt[off+d]=e; sum += e; }
            float inv = __fdividef(1.f, sum);
            for (int d = 0; d < 12; d++) wgt[off+d] *= inv;
        }
    }
    __syncthreads();
    if (tid == 0) bar_arrive_wait(g_bar + 501, 128);
    __syncthreads();

    if (bid >= 8 && bid < 72 && tid < 256) {
        int q = bid - 8;
        float* enc = pool;
        float* wgt = pool + 256;
        float v = enc[tid];
        #pragma unroll
        for (int d = 0; d < 24; d++) v = fmaf(wgt[d], g_cfin[d*256 + tid], v);
        g_qpn[q*256 + tid] = v;
    }
    __syncthreads();
    if (tid == 0) bar_arrive_wait(g_bar + 502, 128);
    __syncthreads();

    if (bid < 32) {
        float* res = pool;
        int c0g = bid * 8;
        if (tid < 256) {
            int w = tid >> 5, ln = tid & 31;
            int q = (w & 1)*32 + ln;
            int rg = w >> 1;
            u64 acc[6];
            #pragma unroll
            for (int j = 0; j < 6; j++) acc[j] = 0ull;
            const float* qrow = g_qpn + (size_t)q*HID;
            #pragma unroll
            for (int ck = 0; ck < 8; ck++) {
                int k0 = ck*32;
                u64 qv[16];
                #pragma unroll
                for (int i = 0; i < 4; i++) {
                    ulonglong2 p = *(const ulonglong2*)(qrow + k0 + i*8);
                    ulonglong2 p2 = *(const ulonglong2*)(qrow + k0 + i*8 + 4);
                    qv[i*4+0]=p.x; qv[i*4+1]=p.y; qv[i*4+2]=p2.x; qv[i*4+3]=p2.y;
                }
                #pragma unroll
                for (int j = 0; j < 6; j++) {
                    int rowIdx = rg*6 + j;
                    int gate = rowIdx >> 3, col = rowIdx & 7;
                    const float* wr = qWih + (size_t)(gate*256 + c0g + col)*HID + k0;
                    #pragma unroll
                    for (int i = 0; i < 4; i++) {
                        ulonglong2 p = *(const ulonglong2*)(wr + i*8);
                        ulonglong2 p2 = *(const ulonglong2*)(wr + i*8 + 4);
                        acc[j] = ffma2(qv[i*4+0], p.x, acc[j]);
                        acc[j] = ffma2(qv[i*4+1], p.y, acc[j]);
                        acc[j] = ffma2(qv[i*4+2], p2.x, acc[j]);
                        acc[j] = ffma2(qv[i*4+3], p2.y, acc[j]);
                    }
                }
            }
            #pragma unroll
            for (int j = 0; j < 6; j++)
                res[(rg*6 + j)*66 + q] = hsum2(acc[j]);
        }
        __syncthreads();
        if (tid < 256) {
            for (int o = tid; o < 512; o += 256) {
                int oq = o >> 3, col = o & 7;
                int c = c0g + col;
                float gr = res[(col)*66 + oq]      + qbih[c];
                float gz = res[(8+col)*66 + oq]    + qbih[256+c];
                float gn = res[(16+col)*66 + oq]   + qbih[512+c];
                float rv = sigf(gr + qbhh[c]);
                float zv = sigf(gz + qbhh[256+c]);
                float nv = tanhfast(gn + rv*qbhh[512+c]);
                out[oq*256 + c] = (1.f - zv)*nv;
            }
        }
    }
}

// ---------------- launch ------------------------------------------------------
extern "C" void kernel_launch(void* const* d_in, const int* in_sizes, int n_in,
                              void* d_out, int out_size) {
    const int*   qt   = (const int*)d_in[0];
    const int*   pt   = (const int*)d_in[1];
    const int*   nt   = (const int*)d_in[2];
    const float* temb = (const float*)d_in[3];
    const float* tWih = (const float*)d_in[4];
    const float* tWhh = (const float*)d_in[5];
    const float* tbih = (const float*)d_in[6];
    const float* tbhh = (const float*)d_in[7];
    const float* demb = (const float*)d_in[8];
    const float* cWih = (const float*)d_in[9];
    const float* cWhh = (const float*)d_in[10];
    const float* cbih = (const float*)d_in[11];
    const float* cbhh = (const float*)d_in[12];
    const float* aWih = (const float*)d_in[13];
    const float* aWhh = (const float*)d_in[14];
    const float* abih = (const float*)d_in[15];
    const float* abhh = (const float*)d_in[16];
    const float* ptab = (const float*)d_in[17];
    const float* posW = (const float*)d_in[18];
    const float* posb = (const float*)d_in[19];
    const float* qWih = (const float*)d_in[20];
    const float* qbih = (const float*)d_in[22];
    const float* qbhh = (const float*)d_in[23];

    gi_gemm_k<<<120, 256>>>(qt, pt, nt, temb, demb,
                            tWih, tbih, cWih, cbih, aWih, abih);

    int smem_bytes = SMEMF * 4;   // 145792
    cudaFuncSetAttribute(scan_k, cudaFuncAttributeMaxDynamicSharedMemorySize, smem_bytes);
    scan_k<<<128, 512, smem_bytes>>>(tWhh, tbhh, cWhh, cbhh, aWhh, abhh,
                                     ptab, posW, posb, qWih, qbih, qbhh, (float*)d_out);
}